// round 2
// baseline (speedup 1.0000x reference)
#include <cuda_runtime.h>

// ---------------------------------------------------------------------------
// LSTM_88244398063643  (T=4096, I=H=1024)
//   Phase 1: xW = x @ W + bias   (fp32 SIMT GEMM, f32x2 packed FMA, BK=16)
//   Phase 2: sequential LSTM scan, 128 persistent blocks, U in registers,
//            flag-based (atomic-free) inter-block sync, h broadcast via L2.
// ---------------------------------------------------------------------------

#define T_STEPS 4096
#define H_DIM   1024
#define I_DIM   1024
#define G4      4096
#define NBLK    128
#define NTHR    512
#define NWARP   16

typedef unsigned long long ull;

__device__ float    g_xW[(size_t)T_STEPS * G4];   // 64 MB scratch
__device__ unsigned g_flags[NBLK];                // per-block epoch flags
__device__ unsigned g_cnt0, g_cnt1;               // end-of-kernel reset barrier

// ---------------- f32x2 helpers --------------------------------------------
__device__ __forceinline__ ull fma2(ull a, ull b, ull c) {
    ull d; asm("fma.rn.f32x2 %0,%1,%2,%3;" : "=l"(d) : "l"(a), "l"(b), "l"(c)); return d;
}
__device__ __forceinline__ ull add2(ull a, ull b) {
    ull d; asm("add.rn.f32x2 %0,%1,%2;" : "=l"(d) : "l"(a), "l"(b)); return d;
}
__device__ __forceinline__ ull dup2(float x) {
    ull d; asm("mov.b64 %0,{%1,%1};" : "=l"(d) : "f"(x)); return d;
}
__device__ __forceinline__ ull pack2(float lo, float hi) {
    ull d; asm("mov.b64 %0,{%1,%2};" : "=l"(d) : "f"(lo), "f"(hi)); return d;
}
__device__ __forceinline__ float2 unpack2(ull v) {
    float lo, hi; asm("mov.b64 {%0,%1},%2;" : "=f"(lo), "=f"(hi) : "l"(v));
    return make_float2(lo, hi);
}

// ---------------- fast activations -----------------------------------------
__device__ __forceinline__ float sigf(float x) {
    return 1.f / (1.f + __expf(-x));
}
__device__ __forceinline__ float tanh_fast(float x) {
    x = fminf(fmaxf(x, -15.f), 15.f);
    float e = __expf(-2.f * x);
    return __fdividef(1.f - e, 1.f + e);
}

// ============================ Phase 1: GEMM ================================
#define BM 128
#define BN 128
#define BK 16

__global__ __launch_bounds__(256, 2) void gemm_xw_kernel(
    const float* __restrict__ A,      // x [4096,1024]
    const float* __restrict__ B,      // W [1024,4096]
    const float* __restrict__ bias)   // [4096]
{
    __shared__ float As[BK][BM];
    __shared__ float Bs[BK][BN];

    const int bx = blockIdx.x, by = blockIdx.y, tid = threadIdx.x;
    const int tx = tid & 15, ty = tid >> 4;

    ull acc[8][4];
#pragma unroll
    for (int i = 0; i < 8; i++)
#pragma unroll
        for (int j = 0; j < 4; j++) acc[i][j] = 0ull;

    const int aRow = tid >> 1, aCol = (tid & 1) * 8;
    const int bRow = tid >> 4, bCol = (tid & 15) * 8;
    const float* Aptr = A + (size_t)(by * BM + aRow) * I_DIM + aCol;
    const float* Bptr = B + (size_t)bRow * G4 + bx * BN + bCol;

    float4 a0 = *(const float4*)(Aptr);
    float4 a1 = *(const float4*)(Aptr + 4);
    float4 b0 = *(const float4*)(Bptr);
    float4 b1 = *(const float4*)(Bptr + 4);

    int k0 = 0;
    for (;;) {
        As[aCol + 0][aRow] = a0.x; As[aCol + 1][aRow] = a0.y;
        As[aCol + 2][aRow] = a0.z; As[aCol + 3][aRow] = a0.w;
        As[aCol + 4][aRow] = a1.x; As[aCol + 5][aRow] = a1.y;
        As[aCol + 6][aRow] = a1.z; As[aCol + 7][aRow] = a1.w;
        *(float4*)&Bs[bRow][bCol]     = b0;
        *(float4*)&Bs[bRow][bCol + 4] = b1;
        __syncthreads();

        k0 += BK;
        const bool more = (k0 < I_DIM);
        if (more) {
            a0 = *(const float4*)(Aptr + k0);
            a1 = *(const float4*)(Aptr + k0 + 4);
            b0 = *(const float4*)(Bptr + (size_t)k0 * G4);
            b1 = *(const float4*)(Bptr + (size_t)k0 * G4 + 4);
        }

#pragma unroll
        for (int k = 0; k < BK; k++) {
            float4 af0 = *(const float4*)&As[k][ty * 8];
            float4 af1 = *(const float4*)&As[k][ty * 8 + 4];
            ulonglong2 bb0 = *(const ulonglong2*)&Bs[k][tx * 8];
            ulonglong2 bb1 = *(const ulonglong2*)&Bs[k][tx * 8 + 4];
            float ar[8] = {af0.x, af0.y, af0.z, af0.w, af1.x, af1.y, af1.z, af1.w};
            ull bp[4] = {bb0.x, bb0.y, bb1.x, bb1.y};
#pragma unroll
            for (int i = 0; i < 8; i++) {
                ull aa = dup2(ar[i]);
                acc[i][0] = fma2(aa, bp[0], acc[i][0]);
                acc[i][1] = fma2(aa, bp[1], acc[i][1]);
                acc[i][2] = fma2(aa, bp[2], acc[i][2]);
                acc[i][3] = fma2(aa, bp[3], acc[i][3]);
            }
        }
        if (!more) break;
        __syncthreads();
    }

#pragma unroll
    for (int i = 0; i < 8; i++) {
        const size_t row = (size_t)(by * BM + ty * 8 + i);
        float* crow = g_xW + row * G4 + bx * BN + tx * 8;
        const float* brow = bias + bx * BN + tx * 8;
#pragma unroll
        for (int j2 = 0; j2 < 4; j2++) {
            float2 c = unpack2(acc[i][j2]);
            crow[2 * j2]     = c.x + brow[2 * j2];
            crow[2 * j2 + 1] = c.y + brow[2 * j2 + 1];
        }
    }
}

// ========================= Phase 2: recurrence =============================
// lane = gate*8 + unit; block owns hidden units [blk*8, blk*8+8)

__device__ __forceinline__ void lstm_update(
    float s, int t, int lane, int blk,
    float& c_state, float& h_last, float* __restrict__ out)
{
    float gf = __shfl_sync(0xffffffffu, s, (lane + 8) & 31);
    float gg = __shfl_sync(0xffffffffu, s, (lane + 16) & 31);
    float go = __shfl_sync(0xffffffffu, s, (lane + 24) & 31);
    if (lane < 8) {
        float iv = sigf(s);
        float fv = sigf(gf);
        float gv = tanh_fast(gg);
        float ov = sigf(go);
        c_state = fv * c_state + iv * gv;
        float hv = ov * tanh_fast(c_state);
        h_last = hv;
        // gather 8 h values to lane 0 for a single-thread release-publish
        float h1 = __shfl_sync(0xffu, hv, 1);
        float h2 = __shfl_sync(0xffu, hv, 2);
        float h3 = __shfl_sync(0xffu, hv, 3);
        float h4 = __shfl_sync(0xffu, hv, 4);
        float h5 = __shfl_sync(0xffu, hv, 5);
        float h6 = __shfl_sync(0xffu, hv, 6);
        float h7 = __shfl_sync(0xffu, hv, 7);
        if (lane == 0) {
            float4* p = reinterpret_cast<float4*>(out + (size_t)t * H_DIM + blk * 8);
            p[0] = make_float4(hv, h1, h2, h3);
            p[1] = make_float4(h4, h5, h6, h7);
            __threadfence();   // h visible before flag
            asm volatile("st.global.cg.u32 [%0], %1;"
                         :: "l"(g_flags + blk), "r"((unsigned)(t + 1)) : "memory");
        }
    }
}

__global__ __launch_bounds__(NTHR, 1) void lstm_rec_kernel(
    const float* __restrict__ U,      // [1024, 4096] row-major
    float* __restrict__ out,
    long long out_size)
{
    __shared__ float part[2][NWARP][32];

    const int tid = threadIdx.x;
    const int wid = tid >> 5;
    const int lane = tid & 31;
    const int blk = blockIdx.x;
    const int unit = lane & 7;
    const int gate = lane >> 3;
    const int gcol = gate * H_DIM + blk * 8 + unit;

    // U slice into registers as packed f32x2 pairs: k = wid*64 + 2j, 2j+1
    ull Ur2[32];
    {
        const float* up = U + (size_t)(wid * 64) * G4 + gcol;
#pragma unroll
        for (int j = 0; j < 32; j++) {
            float lo = up[(size_t)(2 * j) * G4];
            float hi = up[(size_t)(2 * j + 1) * G4];
            Ur2[j] = pack2(lo, hi);
        }
    }

    float c_state = 0.f, h_last = 0.f;

    // ---- step 0: gates = xW[0] (h = 0) ----
    if (wid == 0) {
        float s = g_xW[gcol];
        lstm_update(s, 0, lane, blk, c_state, h_last, out);
    }

    for (int t = 1; t < T_STEPS; t++) {
        // --- poll: warp w needs only its 8 producer blocks (h[64w..64w+63]) ---
        {
            const unsigned need = (unsigned)t;
            const unsigned* fp = g_flags + (wid << 3) + lane;
            unsigned v;
            do {
                v = need;
                if (lane < 8)
                    asm volatile("ld.global.cg.u32 %0,[%1];" : "=r"(v) : "l"(fp));
            } while (__any_sync(0xffffffffu, v < need));
            __threadfence();   // acquire: order h loads after flag observation
        }

        // --- dot: this warp's 64-element h chunk (broadcast L2 loads) ---
        const float* hrow = out + (size_t)(t - 1) * H_DIM + (wid << 6);
        ull a0 = 0ull, a1 = 0ull, a2 = 0ull, a3 = 0ull;
#pragma unroll
        for (int i = 0; i < 16; i++) {
            ull h01, h23;
            asm volatile("ld.global.cg.v2.u64 {%0,%1},[%2];"
                         : "=l"(h01), "=l"(h23) : "l"(hrow + 4 * i));
            if ((i & 1) == 0) {
                a0 = fma2(Ur2[2 * i], h01, a0);
                a1 = fma2(Ur2[2 * i + 1], h23, a1);
            } else {
                a2 = fma2(Ur2[2 * i], h01, a2);
                a3 = fma2(Ur2[2 * i + 1], h23, a3);
            }
        }
        float2 sv = unpack2(add2(add2(a0, a2), add2(a1, a3)));
        part[t & 1][wid][lane] = sv.x + sv.y;

        float xw = 0.f;
        if (wid == 0) xw = g_xW[(size_t)t * G4 + gcol];   // issued before sync

        __syncthreads();   // the only per-step block sync

        if (wid == 0) {
            const float* p = &part[t & 1][0][lane];
            float q0 = p[0 * 32] + p[1 * 32];
            float q1 = p[2 * 32] + p[3 * 32];
            float q2 = p[4 * 32] + p[5 * 32];
            float q3 = p[6 * 32] + p[7 * 32];
            float q4 = p[8 * 32] + p[9 * 32];
            float q5 = p[10 * 32] + p[11 * 32];
            float q6 = p[12 * 32] + p[13 * 32];
            float q7 = p[14 * 32] + p[15 * 32];
            float r0 = q0 + q1, r1 = q2 + q3, r2 = q4 + q5, r3 = q6 + q7;
            float s = xw + ((r0 + r1) + (r2 + r3));
            lstm_update(s, t, lane, blk, c_state, h_last, out);
        }
    }

    // ---- tail: h_T, c_T ----
    if (wid == 0 && lane < 8 &&
        (size_t)out_size >= (size_t)T_STEPS * H_DIM + 2 * H_DIM) {
        out[(size_t)T_STEPS * H_DIM + blk * 8 + lane] = h_last;
        out[(size_t)T_STEPS * H_DIM + H_DIM + blk * 8 + lane] = c_state;
    }

    // ---- replay-safe reset of flags (two-counter ticket barrier) ----
    if (tid == 0) {
        __threadfence();
        atomicAdd(&g_cnt0, 1u);
        unsigned v;
        do {
            asm volatile("ld.global.cg.u32 %0,[%1];" : "=r"(v) : "l"(&g_cnt0));
        } while (v < (unsigned)NBLK);
        asm volatile("st.global.cg.u32 [%0], %1;"
                     :: "l"(g_flags + blk), "r"(0u) : "memory");
        __threadfence();
        if (atomicAdd(&g_cnt1, 1u) == (unsigned)(NBLK - 1)) {
            asm volatile("st.global.cg.u32 [%0], %1;" :: "l"(&g_cnt0), "r"(0u) : "memory");
            asm volatile("st.global.cg.u32 [%0], %1;" :: "l"(&g_cnt1), "r"(0u) : "memory");
        }
    }
}

// =============================== launch ====================================
extern "C" void kernel_launch(void* const* d_in, const int* in_sizes, int n_in,
                              void* d_out, int out_size)
{
    const float* x    = (const float*)d_in[0];
    const float* W    = (const float*)d_in[1];
    const float* U    = (const float*)d_in[2];
    const float* bias = (const float*)d_in[3];
    float* out = (float*)d_out;

    dim3 ggrid(G4 / BN, T_STEPS / BM);
    gemm_xw_kernel<<<ggrid, 256>>>(x, W, bias);

    lstm_rec_kernel<<<NBLK, NTHR>>>(U, out, (long long)out_size);
}

// round 4
// speedup vs baseline: 3.9246x; 3.9246x over previous
#include <cuda_runtime.h>

// ---------------------------------------------------------------------------
// LSTM_88244398063643  (T=4096, I=H=1024)
//   Phase 1: xW = x @ W + bias   (fp32 SIMT GEMM, f32x2 packed FMA, BK=16)
//   Phase 2: sequential scan, 128 persistent blocks, U in registers,
//            per-block epoch flags (128B-strided) + single poll warp/block,
//            h broadcast through L2 via compact double buffer.
// ---------------------------------------------------------------------------

#define T_STEPS 4096
#define H_DIM   1024
#define I_DIM   1024
#define G4      4096
#define NBLK    128
#define NTHR    512
#define NWARP   16
#define FSTRIDE 32            // flags padded to 128B (own L2 line each)

typedef unsigned long long ull;

__device__ float    g_xW[(size_t)T_STEPS * G4];    // 64 MB scratch
__device__ float    g_hbuf[2][H_DIM];              // double-buffered h
__device__ unsigned g_flags[NBLK * FSTRIDE];       // per-block epoch flags
__device__ unsigned g_cnt0, g_cnt1;                // end-of-kernel reset barrier

// ---------------- f32x2 helpers --------------------------------------------
__device__ __forceinline__ ull fma2(ull a, ull b, ull c) {
    ull d; asm("fma.rn.f32x2 %0,%1,%2,%3;" : "=l"(d) : "l"(a), "l"(b), "l"(c)); return d;
}
__device__ __forceinline__ ull add2(ull a, ull b) {
    ull d; asm("add.rn.f32x2 %0,%1,%2;" : "=l"(d) : "l"(a), "l"(b)); return d;
}
__device__ __forceinline__ ull dup2(float x) {
    ull d; asm("mov.b64 %0,{%1,%1};" : "=l"(d) : "f"(x)); return d;
}
__device__ __forceinline__ ull pack2(float lo, float hi) {
    ull d; asm("mov.b64 %0,{%1,%2};" : "=l"(d) : "f"(lo), "f"(hi)); return d;
}
__device__ __forceinline__ float2 unpack2(ull v) {
    float lo, hi; asm("mov.b64 {%0,%1},%2;" : "=f"(lo), "=f"(hi) : "l"(v));
    return make_float2(lo, hi);
}

// ---------------- fast activations -----------------------------------------
__device__ __forceinline__ float sigf(float x) {
    return 1.f / (1.f + __expf(-x));
}
__device__ __forceinline__ float tanh_fast(float x) {
    x = fminf(fmaxf(x, -15.f), 15.f);
    float e = __expf(-2.f * x);
    return __fdividef(1.f - e, 1.f + e);
}

// ============================ Phase 1: GEMM ================================
#define BM 128
#define BN 128
#define BK 16

__global__ __launch_bounds__(256, 2) void gemm_xw_kernel(
    const float* __restrict__ A,      // x [4096,1024]
    const float* __restrict__ B,      // W [1024,4096]
    const float* __restrict__ bias)   // [4096]
{
    __shared__ float As[BK][BM];
    __shared__ float Bs[BK][BN];

    const int bx = blockIdx.x, by = blockIdx.y, tid = threadIdx.x;
    const int tx = tid & 15, ty = tid >> 4;

    ull acc[8][4];
#pragma unroll
    for (int i = 0; i < 8; i++)
#pragma unroll
        for (int j = 0; j < 4; j++) acc[i][j] = 0ull;

    const int aRow = tid >> 1, aCol = (tid & 1) * 8;
    const int bRow = tid >> 4, bCol = (tid & 15) * 8;
    const float* Aptr = A + (size_t)(by * BM + aRow) * I_DIM + aCol;
    const float* Bptr = B + (size_t)bRow * G4 + bx * BN + bCol;

    float4 a0 = *(const float4*)(Aptr);
    float4 a1 = *(const float4*)(Aptr + 4);
    float4 b0 = *(const float4*)(Bptr);
    float4 b1 = *(const float4*)(Bptr + 4);

    int k0 = 0;
    for (;;) {
        As[aCol + 0][aRow] = a0.x; As[aCol + 1][aRow] = a0.y;
        As[aCol + 2][aRow] = a0.z; As[aCol + 3][aRow] = a0.w;
        As[aCol + 4][aRow] = a1.x; As[aCol + 5][aRow] = a1.y;
        As[aCol + 6][aRow] = a1.z; As[aCol + 7][aRow] = a1.w;
        *(float4*)&Bs[bRow][bCol]     = b0;
        *(float4*)&Bs[bRow][bCol + 4] = b1;
        __syncthreads();

        k0 += BK;
        const bool more = (k0 < I_DIM);
        if (more) {
            a0 = *(const float4*)(Aptr + k0);
            a1 = *(const float4*)(Aptr + k0 + 4);
            b0 = *(const float4*)(Bptr + (size_t)k0 * G4);
            b1 = *(const float4*)(Bptr + (size_t)k0 * G4 + 4);
        }

#pragma unroll
        for (int k = 0; k < BK; k++) {
            float4 af0 = *(const float4*)&As[k][ty * 8];
            float4 af1 = *(const float4*)&As[k][ty * 8 + 4];
            ulonglong2 bb0 = *(const ulonglong2*)&Bs[k][tx * 8];
            ulonglong2 bb1 = *(const ulonglong2*)&Bs[k][tx * 8 + 4];
            float ar[8] = {af0.x, af0.y, af0.z, af0.w, af1.x, af1.y, af1.z, af1.w};
            ull bp[4] = {bb0.x, bb0.y, bb1.x, bb1.y};
#pragma unroll
            for (int i = 0; i < 8; i++) {
                ull aa = dup2(ar[i]);
                acc[i][0] = fma2(aa, bp[0], acc[i][0]);
                acc[i][1] = fma2(aa, bp[1], acc[i][1]);
                acc[i][2] = fma2(aa, bp[2], acc[i][2]);
                acc[i][3] = fma2(aa, bp[3], acc[i][3]);
            }
        }
        if (!more) break;
        __syncthreads();
    }

#pragma unroll
    for (int i = 0; i < 8; i++) {
        const size_t row = (size_t)(by * BM + ty * 8 + i);
        float* crow = g_xW + row * G4 + bx * BN + tx * 8;
        const float* brow = bias + bx * BN + tx * 8;
#pragma unroll
        for (int j2 = 0; j2 < 4; j2++) {
            float2 c = unpack2(acc[i][j2]);
            crow[2 * j2]     = c.x + brow[2 * j2];
            crow[2 * j2 + 1] = c.y + brow[2 * j2 + 1];
        }
    }
}

// ========================= Phase 2: recurrence =============================
// lane = gate*8 + unit; block owns hidden units [blk*8, blk*8+8)

__device__ __forceinline__ void lstm_update(
    float s, int t, int lane, int blk,
    float& c_state, float& h_last, float* __restrict__ out)
{
    float gf = __shfl_sync(0xffffffffu, s, (lane + 8) & 31);
    float gg = __shfl_sync(0xffffffffu, s, (lane + 16) & 31);
    float go = __shfl_sync(0xffffffffu, s, (lane + 24) & 31);
    if (lane < 8) {
        float iv = sigf(s);
        float fv = sigf(gf);
        float gv = tanh_fast(gg);
        float ov = sigf(go);
        c_state = fv * c_state + iv * gv;
        float hv = ov * tanh_fast(c_state);
        h_last = hv;
        g_hbuf[t & 1][blk * 8 + lane] = hv;                  // consumed x-block
        out[(size_t)t * H_DIM + blk * 8 + lane] = hv;        // final output
    }
    __syncwarp();
    if (lane == 0) {
        // release: all prior stores (h) visible at gpu scope before the flag
        asm volatile("st.release.gpu.global.u32 [%0], %1;"
                     :: "l"(g_flags + (size_t)blk * FSTRIDE),
                        "r"((unsigned)(t + 1)) : "memory");
    }
}

__global__ __launch_bounds__(NTHR, 1) void lstm_rec_kernel(
    const float* __restrict__ U,      // [1024, 4096] row-major
    float* __restrict__ out,
    long long out_size)
{
    __shared__ __align__(16) float hs[H_DIM];
    __shared__ float part[NWARP][32];

    const int tid = threadIdx.x;
    const int wid = tid >> 5;
    const int lane = tid & 31;
    const int blk = blockIdx.x;
    const int unit = lane & 7;
    const int gate = lane >> 3;
    const int gcol = gate * H_DIM + blk * 8 + unit;

    // U slice into registers as packed f32x2 pairs: k = wid*64 + 2j, 2j+1
    ull Ur2[32];
    {
        const float* up = U + (size_t)(wid * 64) * G4 + gcol;
#pragma unroll
        for (int j = 0; j < 32; j++) {
            float lo = up[(size_t)(2 * j) * G4];
            float hi = up[(size_t)(2 * j + 1) * G4];
            Ur2[j] = pack2(lo, hi);
        }
    }

    float c_state = 0.f, h_last = 0.f;

    // ---- step 0: gates = xW[0] (h = 0) ----
    if (wid == 0) {
        float s = g_xW[gcol];
        lstm_update(s, 0, lane, blk, c_state, h_last, out);
    }

    for (int t = 1; t < T_STEPS; t++) {
        // prefetch xW[t][gcol]: independent of flags, covered by poll wait
        float xw = 0.f;
        if (wid == 0) xw = __ldg(g_xW + (size_t)t * G4 + gcol);

        // --- poll warp: wait until all 128 blocks published h_{t-1} ---
        if (wid == NWARP - 1) {
            const unsigned need = (unsigned)t;
            const unsigned* f0 = g_flags + (size_t)lane * FSTRIDE;
            for (;;) {
                unsigned v0, v1, v2, v3;
                asm volatile("ld.relaxed.gpu.global.u32 %0,[%1];" : "=r"(v0)
                             : "l"(f0 + 0 * 32 * FSTRIDE));
                asm volatile("ld.relaxed.gpu.global.u32 %0,[%1];" : "=r"(v1)
                             : "l"(f0 + 1 * 32 * FSTRIDE));
                asm volatile("ld.relaxed.gpu.global.u32 %0,[%1];" : "=r"(v2)
                             : "l"(f0 + 2 * 32 * FSTRIDE));
                asm volatile("ld.relaxed.gpu.global.u32 %0,[%1];" : "=r"(v3)
                             : "l"(f0 + 3 * 32 * FSTRIDE));
                bool ok = (v0 >= need) & (v1 >= need) & (v2 >= need) & (v3 >= need);
                if (__all_sync(0xffffffffu, ok)) break;
            }
            // acquire + L1 invalidate so weak/cg loads below see fresh h
            asm volatile("fence.acq_rel.gpu;" ::: "memory");
        }
        __syncthreads();   // (A) h_{t-1} globally available

        // --- stage h_{t-1} into smem (compact 4KB buffer, L2-resident) ---
        {
            const float2* hb = (const float2*)g_hbuf[(t - 1) & 1];
            float2 hv = __ldcg(hb + tid);
            *(float2*)&hs[2 * tid] = hv;
        }
        __syncthreads();   // (B)

        // --- dot: warp w handles h[64w .. 64w+63], broadcast LDS.128 ---
        ull a0 = 0ull, a1 = 0ull, a2 = 0ull, a3 = 0ull;
        const ulonglong2* h4 = (const ulonglong2*)&hs[wid << 6];
#pragma unroll
        for (int i = 0; i < 8; i++) {
            ulonglong2 p = h4[2 * i];
            ulonglong2 q = h4[2 * i + 1];
            a0 = fma2(Ur2[4 * i + 0], p.x, a0);
            a1 = fma2(Ur2[4 * i + 1], p.y, a1);
            a2 = fma2(Ur2[4 * i + 2], q.x, a2);
            a3 = fma2(Ur2[4 * i + 3], q.y, a3);
        }
        float2 sv = unpack2(add2(add2(a0, a2), add2(a1, a3)));
        part[wid][lane] = sv.x + sv.y;
        __syncthreads();   // (C)

        // --- warp 0: cross-warp reduce, activations, publish ---
        if (wid == 0) {
            const float* p = &part[0][lane];
            float q0 = p[0 * 32] + p[1 * 32];
            float q1 = p[2 * 32] + p[3 * 32];
            float q2 = p[4 * 32] + p[5 * 32];
            float q3 = p[6 * 32] + p[7 * 32];
            float q4 = p[8 * 32] + p[9 * 32];
            float q5 = p[10 * 32] + p[11 * 32];
            float q6 = p[12 * 32] + p[13 * 32];
            float q7 = p[14 * 32] + p[15 * 32];
            float r0 = q0 + q1, r1 = q2 + q3, r2 = q4 + q5, r3 = q6 + q7;
            float s = xw + ((r0 + r1) + (r2 + r3));
            lstm_update(s, t, lane, blk, c_state, h_last, out);
        }
    }

    // ---- tail: h_T, c_T ----
    if (wid == 0 && lane < 8 &&
        (size_t)out_size >= (size_t)T_STEPS * H_DIM + 2 * H_DIM) {
        out[(size_t)T_STEPS * H_DIM + blk * 8 + lane] = h_last;
        out[(size_t)T_STEPS * H_DIM + H_DIM + blk * 8 + lane] = c_state;
    }

    // ---- replay-safe reset of flags (two-counter ticket barrier) ----
    if (tid == 0) {
        __threadfence();
        atomicAdd(&g_cnt0, 1u);
        unsigned v;
        do {
            asm volatile("ld.relaxed.gpu.global.u32 %0,[%1];" : "=r"(v) : "l"(&g_cnt0));
        } while (v < (unsigned)NBLK);
        asm volatile("st.global.cg.u32 [%0], %1;"
                     :: "l"(g_flags + (size_t)blk * FSTRIDE), "r"(0u) : "memory");
        __threadfence();
        if (atomicAdd(&g_cnt1, 1u) == (unsigned)(NBLK - 1)) {
            asm volatile("st.global.cg.u32 [%0], %1;" :: "l"(&g_cnt0), "r"(0u) : "memory");
            asm volatile("st.global.cg.u32 [%0], %1;" :: "l"(&g_cnt1), "r"(0u) : "memory");
        }
    }
}

// =============================== launch ====================================
extern "C" void kernel_launch(void* const* d_in, const int* in_sizes, int n_in,
                              void* d_out, int out_size)
{
    const float* x    = (const float*)d_in[0];
    const float* W    = (const float*)d_in[1];
    const float* U    = (const float*)d_in[2];
    const float* bias = (const float*)d_in[3];
    float* out = (float*)d_out;

    dim3 ggrid(G4 / BN, T_STEPS / BM);
    gemm_xw_kernel<<<ggrid, 256>>>(x, W, bias);

    lstm_rec_kernel<<<NBLK, NTHR>>>(U, out, (long long)out_size);
}